// round 15
// baseline (speedup 1.0000x reference)
#include <cuda_runtime.h>
#include <cuda_fp16.h>
#include <math.h>

#define NT 128
#define NB 256
#define NC 512
#define HID 256
#define EMB 128
#define NCLS 37
#define NSTEPS 25
#define POSE 256
#define RNN_IN 1472
#define GRU3 768
#define NCTA 592
#define NWARP (NCTA * 8)
#define NJOBS 608

// ---------------- scratch ----------------
__device__ __align__(16) __half g_fp16[NT * NB * HID];
__device__ __align__(16) __half2 g_feats16[NT * NB * NC / 2];
__device__ __align__(16) __half  g_pose16T[NT * NB * POSE];
__device__ __align__(16) __half g_h2h16[HID * HID];
__device__ __align__(16) __half g_i2h16[HID * NC];
__device__ __align__(16) __half g_wih16[GRU3 * RNN_IN];
__device__ __align__(16) __half g_whh16[GRU3 * HID];
__device__ __align__(16) __half g_x16[NB * RNN_IN];
__device__ __align__(16) __half g_hidden16[NB * HID];
__device__ float g_hpp[2][NB * HID];
__device__ float g_gh[2][NB * GRU3];
__device__ float g_gip[10][NB * GRU3];
__device__ float g_hs[NSTEPS * NB * HID];

// barrier + dataflow counters (each on its own 128B line)
__device__ unsigned g_cnt[17 * 32];
__device__ unsigned g_rel[16 * 32];
__device__ unsigned g_rdy_h[4 * 32];
__device__ unsigned g_rdy_hp[4 * 32];   // hp partials ready
__device__ unsigned g_rdy_xf[4 * 32];   // ctx feats ready
__device__ unsigned g_rdy_x[4 * 32];    // ctx pose + emb ready
__device__ unsigned g_rdy_xr[4 * 32];   // crops ready
__device__ unsigned g_rdy_gi[4 * 32];

// ---------------- sync primitives ----------------
__device__ __forceinline__ unsigned ld_acq(const unsigned* p) {
    unsigned v;
    asm volatile("ld.acquire.gpu.global.u32 %0,[%1];" : "=r"(v) : "l"(p) : "memory");
    return v;
}
__device__ __forceinline__ unsigned atom_inc_rel(unsigned* p) {
    unsigned v;
    asm volatile("atom.release.gpu.global.add.u32 %0,[%1],1;" : "=r"(v) : "l"(p) : "memory");
    return v;
}
__device__ __forceinline__ void st_rel(unsigned* p, unsigned v) {
    asm volatile("st.release.gpu.global.u32 [%0],%1;" :: "l"(p), "r"(v) : "memory");
}
__device__ __forceinline__ void spin_ge(const unsigned* p, unsigned tgt) {
    unsigned v = ld_acq(p);
    while ((int)(v - tgt) < 0) { __nanosleep(32); v = ld_acq(p); }
}
__device__ __forceinline__ void gbar() {
    __syncthreads();
    if (threadIdx.x == 0) {
        int g = blockIdx.x / 37;
        unsigned* cnt = &g_cnt[g * 32];
        unsigned* rel = &g_rel[g * 32];
        unsigned gen = ld_acq(rel);
        if (atom_inc_rel(cnt) == 36u) {
            *(volatile unsigned*)cnt = 0u;
            if (atom_inc_rel(&g_cnt[16 * 32]) == 15u) {
                *(volatile unsigned*)&g_cnt[16 * 32] = 0u;
#pragma unroll
                for (int i = 0; i < 16; i++) st_rel(&g_rel[i * 32], gen + 1u);
            } else {
                while (ld_acq(rel) == gen) __nanosleep(32);
            }
        } else {
            while (ld_acq(rel) == gen) __nanosleep(32);
        }
    }
    __syncthreads();
}

// ---------------- fast transcendentals ----------------
__device__ __forceinline__ float fsig(float x) {
    return __fdividef(1.f, 1.f + __expf(-x));
}
__device__ __forceinline__ float ftanh(float x) {
    float r;
    asm("tanh.approx.f32 %0,%1;" : "=f"(r) : "f"(x));
    return r;
}
__device__ __forceinline__ __half2 htanh2(__half2 x) {
    __half2 r;
    asm("tanh.approx.f16x2 %0,%1;" : "=r"(*(unsigned*)&r) : "r"(*(unsigned*)&x));
    return r;
}
__device__ __forceinline__ unsigned h2u(__half2 h) { return *(unsigned*)&h; }

// ---------------- HMMA 64x64 tile: C(f32) = A(f16)@B(f16)^T ----------------
__device__ __forceinline__ void gemm64h(const __half* __restrict__ A, int lda,
                                        const __half* __restrict__ B, int ldb,
                                        float* __restrict__ C, int ldc,
                                        int m0, int n0, int kbase, int ksteps,
                                        int tid)
{
    const int wid = tid >> 5, lane = tid & 31;
    const int g = lane >> 2, ig2 = (lane & 3) * 2;
    const int mb = m0 + (wid >> 2) * 32;
    const int nb = n0 + (wid & 3) * 16;
    float d[2][2][4] = {};
    for (int ks = 0; ks < ksteps; ks++) {
        int k0 = kbase + ks * 16;
        unsigned a[2][4], bf[2][2];
#pragma unroll
        for (int mi = 0; mi < 2; mi++) {
            const __half* ap = A + (size_t)(mb + mi * 16 + g) * lda + k0 + ig2;
            a[mi][0] = __ldcg((const unsigned*)ap);
            a[mi][1] = __ldcg((const unsigned*)(ap + 8 * lda));
            a[mi][2] = __ldcg((const unsigned*)(ap + 8));
            a[mi][3] = __ldcg((const unsigned*)(ap + 8 * lda + 8));
        }
#pragma unroll
        for (int nj = 0; nj < 2; nj++) {
            const __half* bp = B + (size_t)(nb + nj * 8 + g) * ldb + k0 + ig2;
            bf[nj][0] = __ldg((const unsigned*)bp);
            bf[nj][1] = __ldg((const unsigned*)(bp + 8));
        }
#pragma unroll
        for (int mi = 0; mi < 2; mi++)
#pragma unroll
            for (int nj = 0; nj < 2; nj++)
                asm volatile(
                    "mma.sync.aligned.m16n8k16.row.col.f32.f16.f16.f32 "
                    "{%0,%1,%2,%3},{%4,%5,%6,%7},{%8,%9},{%0,%1,%2,%3};"
                    : "+f"(d[mi][nj][0]), "+f"(d[mi][nj][1]),
                      "+f"(d[mi][nj][2]), "+f"(d[mi][nj][3])
                    : "r"(a[mi][0]), "r"(a[mi][1]), "r"(a[mi][2]), "r"(a[mi][3]),
                      "r"(bf[nj][0]), "r"(bf[nj][1]));
    }
#pragma unroll
    for (int mi = 0; mi < 2; mi++) {
        int r = mb + mi * 16 + g;
#pragma unroll
        for (int nj = 0; nj < 2; nj++) {
            int c = nb + nj * 8 + ig2;
            float2 v0 = {d[mi][nj][0], d[mi][nj][1]};
            float2 v1 = {d[mi][nj][2], d[mi][nj][3]};
            *(float2*)(C + (size_t)r * ldc + c) = v0;
            *(float2*)(C + (size_t)(r + 8) * ldc + c) = v1;
        }
    }
}

// ---------------- convert inputs to fp16 ----------------
__device__ __forceinline__ void cvt4(const float* __restrict__ src,
                                     __half* __restrict__ dst, int n4,
                                     int i, int stride)
{
    const float4* s4 = (const float4*)src;
    uint2* d2 = (uint2*)dst;
    for (int j = i; j < n4; j += stride) {
        float4 v = __ldg(s4 + j);
        uint2 u;
        u.x = h2u(__floats2half2_rn(v.x, v.y));
        u.y = h2u(__floats2half2_rn(v.z, v.w));
        d2[j] = u;
    }
}
__global__ __launch_bounds__(256) void convert_kernel(const float* __restrict__ feats,
                                                      const float* __restrict__ i2h_w,
                                                      const float* __restrict__ h2h_w,
                                                      const float* __restrict__ gru_w_ih,
                                                      const float* __restrict__ gru_w_hh)
{
    int i = blockIdx.x * 256 + threadIdx.x;
    int stride = gridDim.x * 256;
    cvt4(feats, (__half*)g_feats16, NT * NB * NC / 4, i, stride);
    cvt4(i2h_w, g_i2h16, HID * NC / 4, i, stride);
    cvt4(h2h_w, g_h2h16, HID * HID / 4, i, stride);
    cvt4(gru_w_ih, g_wih16, GRU3 * RNN_IN / 4, i, stride);
    cvt4(gru_w_hh, g_whh16, GRU3 * HID / 4, i, stride);
}

// ---------------- feats_proj via HMMA ----------------
__global__ __launch_bounds__(256) void fp_gemm_hmma()
{
    const int tid = threadIdx.x;
    const int wid = tid >> 5, lane = tid & 31;
    const int g = lane >> 2, ig2 = (lane & 3) * 2;
    const int warp_m = wid >> 1, warp_n = wid & 1;
    const int mbase = blockIdx.y * 128 + warp_m * 32;
    const int nbase = blockIdx.x * 128 + warp_n * 64;
    const __half* A = (const __half*)g_feats16;

    float d[2][8][4] = {};
    for (int k0 = 0; k0 < NC; k0 += 16) {
        unsigned a[2][4], b[8][2];
#pragma unroll
        for (int mi = 0; mi < 2; mi++) {
            const __half* ap = A + (size_t)(mbase + mi * 16 + g) * NC + k0 + ig2;
            a[mi][0] = *(const unsigned*)ap;
            a[mi][1] = *(const unsigned*)(ap + 8 * NC);
            a[mi][2] = *(const unsigned*)(ap + 8);
            a[mi][3] = *(const unsigned*)(ap + 8 * NC + 8);
        }
#pragma unroll
        for (int nj = 0; nj < 8; nj++) {
            const __half* bp = g_i2h16 + (size_t)(nbase + nj * 8 + g) * NC + k0 + ig2;
            b[nj][0] = *(const unsigned*)bp;
            b[nj][1] = *(const unsigned*)(bp + 8);
        }
#pragma unroll
        for (int mi = 0; mi < 2; mi++)
#pragma unroll
            for (int nj = 0; nj < 8; nj++)
                asm volatile(
                    "mma.sync.aligned.m16n8k16.row.col.f32.f16.f16.f32 "
                    "{%0,%1,%2,%3},{%4,%5,%6,%7},{%8,%9},{%0,%1,%2,%3};"
                    : "+f"(d[mi][nj][0]), "+f"(d[mi][nj][1]),
                      "+f"(d[mi][nj][2]), "+f"(d[mi][nj][3])
                    : "r"(a[mi][0]), "r"(a[mi][1]), "r"(a[mi][2]), "r"(a[mi][3]),
                      "r"(b[nj][0]), "r"(b[nj][1]));
    }
#pragma unroll
    for (int mi = 0; mi < 2; mi++) {
        int r = mbase + mi * 16 + g;
#pragma unroll
        for (int nj = 0; nj < 8; nj++) {
            int c = nbase + nj * 8 + ig2;
            *(__half2*)(g_fp16 + (size_t)r * HID + c) =
                __floats2half2_rn(d[mi][nj][0], d[mi][nj][1]);
            *(__half2*)(g_fp16 + (size_t)(r + 8) * HID + c) =
                __floats2half2_rn(d[mi][nj][2], d[mi][nj][3]);
        }
    }
}

// ---------------- GRU update (hold from smem) ----------------
__device__ __forceinline__ float gru_one(int b, int h, float hold,
                                         const float* __restrict__ gru_b_ih,
                                         const float* __restrict__ gru_b_hh)
{
    size_t base = (size_t)b * GRU3;
    float ir = __ldg(gru_b_ih + h);
    float iz = __ldg(gru_b_ih + HID + h);
    float in = __ldg(gru_b_ih + 2 * HID + h);
#pragma unroll
    for (int p = 0; p < 10; p++) {
        ir += __ldcg(&g_gip[p][base + h]);
        iz += __ldcg(&g_gip[p][base + HID + h]);
        in += __ldcg(&g_gip[p][base + 2 * HID + h]);
    }
    float hr = __ldg(gru_b_hh + h)           + __ldcg(&g_gh[0][base + h])           + __ldcg(&g_gh[1][base + h]);
    float hz = __ldg(gru_b_hh + HID + h)     + __ldcg(&g_gh[0][base + HID + h])     + __ldcg(&g_gh[1][base + HID + h]);
    float hn = __ldg(gru_b_hh + 2 * HID + h) + __ldcg(&g_gh[0][base + 2 * HID + h]) + __ldcg(&g_gh[1][base + 2 * HID + h]);
    float rr = fsig(ir + hr);
    float zz = fsig(iz + hz);
    float nn = ftanh(in + rr * hn);
    return (1.f - zz) * nn + zz * hold;
}

// ---------------- B-CTA GEMM job ----------------
// jobs: 0-31 hp | 32-127 gh | 128-607 gi
__device__ __forceinline__ void run_job(int j, int step, int tid)
{
    if (j < 32) {
        int ks = j / 16, r = j % 16, mt = r / 4, nt = r % 4;
        if (tid == 0) spin_ge(&g_rdy_h[mt * 32], 64u * (step + 1));
        __syncthreads();
        gemm64h(g_hidden16, HID, g_h2h16, HID, g_hpp[ks], HID,
                mt * 64, nt * 64, ks * 128, 8, tid);
        __syncthreads();
        if (tid == 0) atom_inc_rel(&g_rdy_hp[mt * 32]);
    } else if (j < 128) {
        int jj = j - 32;
        int ks = jj / 48, r = jj % 48, mt = r / 12, nt = r % 12;
        if (tid == 0) spin_ge(&g_rdy_h[mt * 32], 64u * (step + 1));
        __syncthreads();
        gemm64h(g_hidden16, HID, g_whh16, HID, g_gh[ks], GRU3,
                mt * 64, nt * 64, ks * 128, 8, tid);
        __syncthreads();
        if (tid == 0) atom_inc_rel(&g_rdy_gi[mt * 32]);
    } else {
        // splits: 0-3 feats(K 0..512) -> rdy_xf ; 4-5 pose+emb(512..896) -> rdy_x ;
        //         6-9 crops(896..1472) -> rdy_xr
        const int kb[10] = {0, 128, 256, 384, 512, 704, 896, 1040, 1184, 1328};
        const int ki[10] = {8, 8, 8, 8, 12, 12, 9, 9, 9, 9};
        int jj = j - 128;
        int ks = jj / 48, r = jj % 48, mt = r / 12, nt = r % 12;
        const unsigned* ctr = (ks < 4) ? &g_rdy_xf[mt * 32]
                            : (ks < 6) ? &g_rdy_x[mt * 32]
                                       : &g_rdy_xr[mt * 32];
        if (tid == 0) spin_ge(ctr, 64u * (step + 1));
        __syncthreads();
        gemm64h(g_x16, RNN_IN, g_wih16, RNN_IN, g_gip[ks], GRU3,
                mt * 64, nt * 64, kb[ks], ki[ks], tid);
        __syncthreads();
        if (tid == 0) atom_inc_rel(&g_rdy_gi[mt * 32]);
    }
}

// ---------------- persistent decode kernel ----------------
__global__ __launch_bounds__(256, 4) void decode_kernel(
    const float* __restrict__ pose,
    const float* __restrict__ pyr0,
    const float* __restrict__ pyr1,
    const float* __restrict__ pyr2,
    const int*   __restrict__ text,
    const float* __restrict__ h2h_b,
    const float* __restrict__ score_w,
    const float* __restrict__ pose_w,   const float* __restrict__ pose_b,
    const float* __restrict__ gru_b_ih, const float* __restrict__ gru_b_hh,
    const float* __restrict__ char_emb,
    const float* __restrict__ gen_w,    const float* __restrict__ gen_b,
    float* __restrict__ out)
{
    __shared__ __align__(16) float sm[4352];
    __shared__ float s_coord[4];
    __shared__ float s_ly[3][2], s_lx[3][2];
    __shared__ int   s_y0[3][2], s_y1[3][2], s_x0[3][2], s_x1[3][2];
    __shared__ int   s_vy[3][2], s_vx[3][2];

    const int tid = threadIdx.x;
    const int bid = blockIdx.x;
    const int lane = tid & 31;
    const int wid = tid >> 5;

    float* h_s   = sm;          // persistent hidden (per A-CTA)
    float* hp_s  = sm + 256;
    float* al    = sm + 512;
    float* ctx_s = sm + 640;
    float* red   = sm + 1408;

    // ---- prologue: counters, hidden16, pose transpose ----
    if (bid == 0) {
        for (int i = tid; i < 4 * 32; i += 256) {
            g_rdy_h[i] = 0u; g_rdy_hp[i] = 0u; g_rdy_xf[i] = 0u;
            g_rdy_x[i] = 0u; g_rdy_xr[i] = 0u; g_rdy_gi[i] = 0u;
        }
    }
    if (bid < 256) g_hidden16[bid * 256 + tid] = __float2half(0.f);
    for (int job = bid; job < NB * 32; job += NCTA) {
        int b = job >> 5;
        int r = job & 31;
        int t0 = (r & 3) * 32;
        int p0 = (r >> 2) * 32;
        int y = tid >> 5, x = tid & 31;
#pragma unroll
        for (int q = 0; q < 4; q++) {
            int yy = y + q * 8;
            red[yy * 33 + x] = __ldg(pose + ((size_t)b * POSE + (p0 + yy)) * NT + (t0 + x));
        }
        __syncthreads();
#pragma unroll
        for (int q = 0; q < 4; q++) {
            int yy = y + q * 8;
            g_pose16T[((size_t)(t0 + yy) * NB + b) * POSE + (p0 + x)] =
                __float2half(red[x * 33 + yy]);
        }
        __syncthreads();
    }
    h_s[tid] = 0.f;
    gbar();

    if (bid < NB) {
        // ================= A-CTA: full recurrence for b = bid =================
        const int b = bid;
        const int mt = b >> 6;
        for (int step = 0; step < NSTEPS; step++) {
            float hnew = 0.f;
            if (step > 0) {
                if (tid == 0) spin_ge(&g_rdy_gi[mt * 32], 144u * (unsigned)step);
                __syncthreads();
                hnew = gru_one(b, tid, h_s[tid], gru_b_ih, gru_b_hh);
                g_hidden16[(size_t)b * HID + tid] = __float2half(hnew);
                h_s[tid] = hnew;
                __syncthreads();
                if (tid == 0) atom_inc_rel(&g_rdy_h[mt * 32]);
                g_hs[((size_t)b * NSTEPS + step - 1) * HID + tid] = hnew;
            } else {
                if (tid == 0) atom_inc_rel(&g_rdy_h[mt * 32]);
            }

            // emb (safe: previous-step consumers finished per gi-counter spin)
            int tgt = (step == 0) ? 0 : (__ldg(text + b * NSTEPS + step - 1) + 1);
            if (tid < EMB)
                g_x16[(size_t)b * RNN_IN + 768 + tid] =
                    __float2half(__ldg(char_emb + (size_t)tgt * EMB + tid));

            // hp from B-side partials
            if (tid == 0) spin_ge(&g_rdy_hp[mt * 32], 8u * (step + 1));
            __syncthreads();
            hp_s[tid] = __ldcg(&g_hpp[0][(size_t)b * HID + tid])
                      + __ldcg(&g_hpp[1][(size_t)b * HID + tid])
                      + __ldg(h2h_b + tid);
            __syncthreads();

            // energy
            {
                float4 hpa = *(const float4*)&hp_s[lane * 8];
                float4 hpb = *(const float4*)&hp_s[lane * 8 + 4];
                __half2 hph[4] = {
                    __floats2half2_rn(hpa.x, hpa.y), __floats2half2_rn(hpa.z, hpa.w),
                    __floats2half2_rn(hpb.x, hpb.y), __floats2half2_rn(hpb.z, hpb.w)};
                float4 swa = __ldg((const float4*)(score_w + lane * 8));
                float4 swb = __ldg((const float4*)(score_w + lane * 8 + 4));
                float swf[8] = {swa.x, swa.y, swa.z, swa.w, swb.x, swb.y, swb.z, swb.w};
#pragma unroll
                for (int i = 0; i < 16; i++) {
                    int t = wid * 16 + i;
                    uint4 fv = __ldg((const uint4*)(g_fp16 + ((size_t)t * NB + b) * HID + lane * 8));
                    __half2 v0 = *(__half2*)&fv.x, v1 = *(__half2*)&fv.y;
                    __half2 v2 = *(__half2*)&fv.z, v3 = *(__half2*)&fv.w;
                    float2 t0 = __half22float2(htanh2(__hadd2(v0, hph[0])));
                    float2 t1 = __half22float2(htanh2(__hadd2(v1, hph[1])));
                    float2 t2 = __half22float2(htanh2(__hadd2(v2, hph[2])));
                    float2 t3 = __half22float2(htanh2(__hadd2(v3, hph[3])));
                    float s = t0.x * swf[0] + t0.y * swf[1] + t1.x * swf[2] + t1.y * swf[3]
                            + t2.x * swf[4] + t2.y * swf[5] + t3.x * swf[6] + t3.y * swf[7];
#pragma unroll
                    for (int o = 16; o; o >>= 1) s += __shfl_xor_sync(~0u, s, o);
                    if (!lane) al[t] = s;
                }
            }
            __syncthreads();
            if (wid == 0) {
                float ev[4];
#pragma unroll
                for (int q = 0; q < 4; q++) ev[q] = al[lane + 32 * q];
                float mx = fmaxf(fmaxf(ev[0], ev[1]), fmaxf(ev[2], ev[3]));
#pragma unroll
                for (int o = 16; o; o >>= 1) mx = fmaxf(mx, __shfl_xor_sync(~0u, mx, o));
                float ex[4], ssum = 0.f;
#pragma unroll
                for (int q = 0; q < 4; q++) { ex[q] = __expf(ev[q] - mx); ssum += ex[q]; }
#pragma unroll
                for (int o = 16; o; o >>= 1) ssum += __shfl_xor_sync(~0u, ssum, o);
                float inv = __fdividef(1.f, ssum);
#pragma unroll
                for (int q = 0; q < 4; q++) al[lane + 32 * q] = ex[q] * inv;
            }
            __syncthreads();
            // ctx feats
            {
                int tq = tid >> 6, cg = tid & 63;
                float acc[8] = {};
                int t0 = tq * 32;
#pragma unroll 8
                for (int i = 0; i < 32; i++) {
                    int t = t0 + i;
                    uint4 u = __ldg((const uint4*)(g_feats16 + ((size_t)t * NB + b) * (NC / 2)) + cg);
                    float a = al[t];
                    const __half2* h2 = (const __half2*)&u;
#pragma unroll
                    for (int q = 0; q < 4; q++) {
                        float2 f = __half22float2(h2[q]);
                        acc[2 * q]     = fmaf(a, f.x, acc[2 * q]);
                        acc[2 * q + 1] = fmaf(a, f.y, acc[2 * q + 1]);
                    }
                }
#pragma unroll
                for (int q = 0; q < 8; q++) red[tq * 512 + cg * 8 + q] = acc[q];
            }
            __syncthreads();
            {
                int c = tid * 2;
                float s0 = red[c] + red[512 + c] + red[1024 + c] + red[1536 + c];
                float s1 = red[c + 1] + red[512 + c + 1] + red[1024 + c + 1] + red[1536 + c + 1];
                ctx_s[c] = s0; ctx_s[c + 1] = s1;
                *(__half2*)(g_x16 + (size_t)b * RNN_IN + c) = __floats2half2_rn(s0, s1);
            }
            __syncthreads();
            if (tid == 0) atom_inc_rel(&g_rdy_xf[mt * 32]);
            // ctx pose
            {
                int tq2 = tid >> 5, cg2 = tid & 31;
                float acc[8] = {};
                int t0 = tq2 * 16;
#pragma unroll 8
                for (int i = 0; i < 16; i++) {
                    int t = t0 + i;
                    uint4 u = __ldg((const uint4*)(g_pose16T + ((size_t)t * NB + b) * POSE) + cg2);
                    float a = al[t];
                    const __half2* h2 = (const __half2*)&u;
#pragma unroll
                    for (int q = 0; q < 4; q++) {
                        float2 f = __half22float2(h2[q]);
                        acc[2 * q]     = fmaf(a, f.x, acc[2 * q]);
                        acc[2 * q + 1] = fmaf(a, f.y, acc[2 * q + 1]);
                    }
                }
#pragma unroll
                for (int q = 0; q < 8; q++) red[tq2 * 256 + cg2 * 8 + q] = acc[q];
            }
            __syncthreads();
            {
                int c = tid;
                float s = 0.f;
#pragma unroll
                for (int q = 0; q < 8; q++) s += red[q * 256 + c];
                ctx_s[NC + c] = s;
                g_x16[(size_t)b * RNN_IN + NC + c] = __float2half(s);
            }
            __syncthreads();
            if (tid == 0) atom_inc_rel(&g_rdy_x[mt * 32]);
            // coord
            if (wid < 4) {
                const float* pw = pose_w + wid * 768;
                float s = 0.f;
#pragma unroll
                for (int q = 0; q < 24; q++) { int c = lane + q * 32; s += ctx_s[c] * __ldg(pw + c); }
#pragma unroll
                for (int o = 16; o; o >>= 1) s += __shfl_xor_sync(~0u, s, o);
                if (!lane) s_coord[wid] = fsig(s + __ldg(pose_b + wid));
            }
            __syncthreads();
            if (tid == 0) {
                const int Hs[3] = {16, 8, 4};
                const int Ws[3] = {128, 64, 65};
                float c0 = s_coord[0], c1 = s_coord[1], c2 = s_coord[2], c3 = s_coord[3];
                for (int p = 0; p < 3; p++) {
                    float Hf = (float)Hs[p], Wf = (float)Ws[p];
                    c0 *= Hf; c1 *= Wf; c2 *= Hf; c3 *= Wf;
                    float x1 = c0, y1 = c1, x2 = c2, y2 = c3;
                    float bw = fmaxf(x2 - x1, 1.f) * 0.5f;
                    float bh = fmaxf(y2 - y1, 1.f) * 0.5f;
#pragma unroll
                    for (int i = 0; i < 2; i++) {
                        float ys = y1 + (0.5f + (float)i) * bh;
                        s_vy[p][i] = (ys >= -1.f && ys <= Hf) ? 1 : 0;
                        float y = fminf(fmaxf(ys, 0.f), Hf - 1.f);
                        float y0f = floorf(y);
                        int y0i = (int)y0f;
                        s_y0[p][i] = y0i;
                        s_y1[p][i] = min(y0i + 1, Hs[p] - 1);
                        s_ly[p][i] = y - y0f;
                        float xs = x1 + (0.5f + (float)i) * bw;
                        s_vx[p][i] = (xs >= -1.f && xs <= Wf) ? 1 : 0;
                        float x = fminf(fmaxf(xs, 0.f), Wf - 1.f);
                        float x0f = floorf(x);
                        int x0i = (int)x0f;
                        s_x0[p][i] = x0i;
                        s_x1[p][i] = min(x0i + 1, Ws[p] - 1);
                        s_lx[p][i] = x - x0f;
                    }
                }
            }
            __syncthreads();
            for (int o = tid; o < 576; o += 256) {
                int p, local;
                if (o < 64)       { p = 0; local = o; }
                else if (o < 320) { p = 1; local = o - 64; }
                else              { p = 2; local = o - 320; }
                int c = local >> 2;
                int ij = local & 3;
                int i = ij >> 1, j = ij & 1;
                float val = 0.f;
                if (s_vy[p][i] && s_vx[p][j]) {
                    float ly = s_ly[p][i], lx = s_lx[p][j];
                    float hy = 1.f - ly, hx = 1.f - lx;
                    int y0 = s_y0[p][i], y1 = s_y1[p][i];
                    int x0 = s_x0[p][j], x1 = s_x1[p][j];
                    const float* f; int W, HW;
                    if (p == 0)      { f = pyr0; W = 128; HW = 16 * 128; }
                    else if (p == 1) { f = pyr1; W = 64;  HW = 8 * 64;  }
                    else             { f = pyr2; W = 65;  HW = 4 * 65;  }
                    const float* fc = f + (size_t)c * HW;
                    val = fc[y0 * W + x0] * (hy * hx)
                        + fc[y0 * W + x1] * (hy * lx)
                        + fc[y1 * W + x0] * (ly * hx)
                        + fc[y1 * W + x1] * (ly * lx);
                }
                g_x16[(size_t)b * RNN_IN + 896 + o] = __float2half(val);
            }
            __syncthreads();
            if (tid == 0) atom_inc_rel(&g_rdy_xr[mt * 32]);
        }
        // final GRU
        if (tid == 0) spin_ge(&g_rdy_gi[mt * 32], 144u * NSTEPS);
        __syncthreads();
        float hnew = gru_one(b, tid, h_s[tid], gru_b_ih, gru_b_hh);
        g_hs[((size_t)b * NSTEPS + NSTEPS - 1) * HID + tid] = hnew;
    } else {
        // ================= B-CTA: 1-2 GEMM jobs per step =================
        int s = bid - 256;
        int ja = s;                      // s<128 -> hp/gh (run first); else early gi
        int jb = (s + 336 < NJOBS) ? s + 336 : -1;   // late gi splits
        for (int step = 0; step < NSTEPS; step++) {
            run_job(ja, step, tid);
            if (jb >= 0) run_job(jb, step, tid);
        }
    }
    gbar();

    // ===== final classifier =====
    {
        int gw = bid * 8 + wid;
        for (int m = gw; m < NB * NSTEPS; m += NWARP) {
            const float* hrow = g_hs + (size_t)m * HID;
            float a[8];
#pragma unroll
            for (int q = 0; q < 8; q++) a[q] = __ldcg(hrow + lane + q * 32);
            for (int n = 0; n < NCLS; n++) {
                const float* w = gen_w + (size_t)n * HID;
                float s = 0.f;
#pragma unroll
                for (int q = 0; q < 8; q++) s += a[q] * __ldg(w + lane + q * 32);
#pragma unroll
                for (int o = 16; o; o >>= 1) s += __shfl_xor_sync(~0u, s, o);
                if (!lane) out[(size_t)m * NCLS + n] = s + gen_b[n];
            }
        }
    }
}

// ---------------- driver ----------------
extern "C" void kernel_launch(void* const* d_in, const int* in_sizes, int n_in,
                              void* d_out, int out_size)
{
    const float* feats    = (const float*)d_in[0];
    const float* pose     = (const float*)d_in[1];
    const float* pyr0     = (const float*)d_in[2];
    const float* pyr1     = (const float*)d_in[3];
    const float* pyr2     = (const float*)d_in[4];
    const int*   text     = (const int*)  d_in[6];
    const float* i2h_w    = (const float*)d_in[7];
    const float* h2h_w    = (const float*)d_in[8];
    const float* h2h_b    = (const float*)d_in[9];
    const float* score_w  = (const float*)d_in[10];
    const float* pose_w   = (const float*)d_in[11];
    const float* pose_b   = (const float*)d_in[12];
    const float* gru_w_ih = (const float*)d_in[13];
    const float* gru_w_hh = (const float*)d_in[14];
    const float* gru_b_ih = (const float*)d_in[15];
    const float* gru_b_hh = (const float*)d_in[16];
    const float* char_emb = (const float*)d_in[17];
    const float* gen_w    = (const float*)d_in[18];
    const float* gen_b    = (const float*)d_in[19];
    float* out = (float*)d_out;

    convert_kernel<<<1184, 256>>>(feats, i2h_w, h2h_w, gru_w_ih, gru_w_hh);

    dim3 g1(2, 256);
    fp_gemm_hmma<<<g1, 256>>>();

    decode_kernel<<<NCTA, 256>>>(pose, pyr0, pyr1, pyr2, text,
                                 h2h_b, score_w, pose_w, pose_b,
                                 gru_b_ih, gru_b_hh,
                                 char_emb, gen_w, gen_b, out);
}

// round 16
// speedup vs baseline: 1.1020x; 1.1020x over previous
#include <cuda_runtime.h>
#include <cuda_fp16.h>
#include <math.h>

#define NT 128
#define NB 256
#define NC 512
#define HID 256
#define EMB 128
#define NCLS 37
#define NSTEPS 25
#define POSE 256
#define RNN_IN 1472
#define GRU3 768
#define NCTA 592
#define NWARP (NCTA * 8)

// ---------------- scratch ----------------
__device__ __align__(16) __half g_fp16[NT * NB * HID];
__device__ __align__(16) __half2 g_feats16[NT * NB * NC / 2];
__device__ __align__(16) __half  g_pose16T[NT * NB * POSE];
__device__ __align__(16) __half g_h2h16[HID * HID];
__device__ __align__(16) __half g_i2h16[HID * NC];
__device__ __align__(16) __half g_wih16[GRU3 * RNN_IN];
__device__ __align__(16) __half g_whh16[GRU3 * HID];
__device__ __align__(16) __half g_x16[NB * RNN_IN];
__device__ __align__(16) __half g_hidden16[NB * HID];
__device__ float g_gh[2][NB * GRU3];
__device__ float g_gip[10][NB * GRU3];
__device__ float g_hs[NSTEPS * NB * HID];

// barrier + dataflow counters (each on its own 128B line)
__device__ unsigned g_cnt[17 * 32];
__device__ unsigned g_rel[16 * 32];
__device__ unsigned g_rdy_h[4 * 32];
__device__ unsigned g_rdy_xf[4 * 32];   // ctx feats ready
__device__ unsigned g_rdy_x[4 * 32];    // ctx pose + emb ready
__device__ unsigned g_rdy_xr[4 * 32];   // crops ready
__device__ unsigned g_rdy_gi[4 * 32];

// ---------------- sync primitives ----------------
__device__ __forceinline__ unsigned ld_acq(const unsigned* p) {
    unsigned v;
    asm volatile("ld.acquire.gpu.global.u32 %0,[%1];" : "=r"(v) : "l"(p) : "memory");
    return v;
}
__device__ __forceinline__ unsigned atom_inc_rel(unsigned* p) {
    unsigned v;
    asm volatile("atom.release.gpu.global.add.u32 %0,[%1],1;" : "=r"(v) : "l"(p) : "memory");
    return v;
}
__device__ __forceinline__ void st_rel(unsigned* p, unsigned v) {
    asm volatile("st.release.gpu.global.u32 [%0],%1;" :: "l"(p), "r"(v) : "memory");
}
__device__ __forceinline__ void spin_ge(const unsigned* p, unsigned tgt) {
    unsigned v = ld_acq(p);
    while ((int)(v - tgt) < 0) { __nanosleep(32); v = ld_acq(p); }
}
__device__ __forceinline__ void gbar() {
    __syncthreads();
    if (threadIdx.x == 0) {
        int g = blockIdx.x / 37;
        unsigned* cnt = &g_cnt[g * 32];
        unsigned* rel = &g_rel[g * 32];
        unsigned gen = ld_acq(rel);
        if (atom_inc_rel(cnt) == 36u) {
            *(volatile unsigned*)cnt = 0u;
            if (atom_inc_rel(&g_cnt[16 * 32]) == 15u) {
                *(volatile unsigned*)&g_cnt[16 * 32] = 0u;
#pragma unroll
                for (int i = 0; i < 16; i++) st_rel(&g_rel[i * 32], gen + 1u);
            } else {
                while (ld_acq(rel) == gen) __nanosleep(32);
            }
        } else {
            while (ld_acq(rel) == gen) __nanosleep(32);
        }
    }
    __syncthreads();
}

// ---------------- fast transcendentals ----------------
__device__ __forceinline__ float fsig(float x) {
    return __fdividef(1.f, 1.f + __expf(-x));
}
__device__ __forceinline__ float ftanh(float x) {
    float r;
    asm("tanh.approx.f32 %0,%1;" : "=f"(r) : "f"(x));
    return r;
}
__device__ __forceinline__ __half2 htanh2(__half2 x) {
    __half2 r;
    asm("tanh.approx.f16x2 %0,%1;" : "=r"(*(unsigned*)&r) : "r"(*(unsigned*)&x));
    return r;
}
__device__ __forceinline__ unsigned h2u(__half2 h) { return *(unsigned*)&h; }

// ---------------- HMMA 64x64 tile: C(f32) = A(f16)@B(f16)^T ----------------
__device__ __forceinline__ void gemm64h(const __half* __restrict__ A, int lda,
                                        const __half* __restrict__ B, int ldb,
                                        float* __restrict__ C, int ldc,
                                        int m0, int n0, int kbase, int ksteps,
                                        int tid)
{
    const int wid = tid >> 5, lane = tid & 31;
    const int g = lane >> 2, ig2 = (lane & 3) * 2;
    const int mb = m0 + (wid >> 2) * 32;
    const int nb = n0 + (wid & 3) * 16;
    float d[2][2][4] = {};
    for (int ks = 0; ks < ksteps; ks++) {
        int k0 = kbase + ks * 16;
        unsigned a[2][4], bf[2][2];
#pragma unroll
        for (int mi = 0; mi < 2; mi++) {
            const __half* ap = A + (size_t)(mb + mi * 16 + g) * lda + k0 + ig2;
            a[mi][0] = __ldcg((const unsigned*)ap);
            a[mi][1] = __ldcg((const unsigned*)(ap + 8 * lda));
            a[mi][2] = __ldcg((const unsigned*)(ap + 8));
            a[mi][3] = __ldcg((const unsigned*)(ap + 8 * lda + 8));
        }
#pragma unroll
        for (int nj = 0; nj < 2; nj++) {
            const __half* bp = B + (size_t)(nb + nj * 8 + g) * ldb + k0 + ig2;
            bf[nj][0] = __ldg((const unsigned*)bp);
            bf[nj][1] = __ldg((const unsigned*)(bp + 8));
        }
#pragma unroll
        for (int mi = 0; mi < 2; mi++)
#pragma unroll
            for (int nj = 0; nj < 2; nj++)
                asm volatile(
                    "mma.sync.aligned.m16n8k16.row.col.f32.f16.f16.f32 "
                    "{%0,%1,%2,%3},{%4,%5,%6,%7},{%8,%9},{%0,%1,%2,%3};"
                    : "+f"(d[mi][nj][0]), "+f"(d[mi][nj][1]),
                      "+f"(d[mi][nj][2]), "+f"(d[mi][nj][3])
                    : "r"(a[mi][0]), "r"(a[mi][1]), "r"(a[mi][2]), "r"(a[mi][3]),
                      "r"(bf[nj][0]), "r"(bf[nj][1]));
    }
#pragma unroll
    for (int mi = 0; mi < 2; mi++) {
        int r = mb + mi * 16 + g;
#pragma unroll
        for (int nj = 0; nj < 2; nj++) {
            int c = nb + nj * 8 + ig2;
            float2 v0 = {d[mi][nj][0], d[mi][nj][1]};
            float2 v1 = {d[mi][nj][2], d[mi][nj][3]};
            *(float2*)(C + (size_t)r * ldc + c) = v0;
            *(float2*)(C + (size_t)(r + 8) * ldc + c) = v1;
        }
    }
}

// ---------------- convert inputs to fp16 ----------------
__device__ __forceinline__ void cvt4(const float* __restrict__ src,
                                     __half* __restrict__ dst, int n4,
                                     int i, int stride)
{
    const float4* s4 = (const float4*)src;
    uint2* d2 = (uint2*)dst;
    for (int j = i; j < n4; j += stride) {
        float4 v = __ldg(s4 + j);
        uint2 u;
        u.x = h2u(__floats2half2_rn(v.x, v.y));
        u.y = h2u(__floats2half2_rn(v.z, v.w));
        d2[j] = u;
    }
}
__global__ __launch_bounds__(256) void convert_kernel(const float* __restrict__ feats,
                                                      const float* __restrict__ i2h_w,
                                                      const float* __restrict__ h2h_w,
                                                      const float* __restrict__ gru_w_ih,
                                                      const float* __restrict__ gru_w_hh)
{
    int i = blockIdx.x * 256 + threadIdx.x;
    int stride = gridDim.x * 256;
    cvt4(feats, (__half*)g_feats16, NT * NB * NC / 4, i, stride);
    cvt4(i2h_w, g_i2h16, HID * NC / 4, i, stride);
    cvt4(h2h_w, g_h2h16, HID * HID / 4, i, stride);
    cvt4(gru_w_ih, g_wih16, GRU3 * RNN_IN / 4, i, stride);
    cvt4(gru_w_hh, g_whh16, GRU3 * HID / 4, i, stride);
}

// ---------------- feats_proj via HMMA ----------------
__global__ __launch_bounds__(256) void fp_gemm_hmma()
{
    const int tid = threadIdx.x;
    const int wid = tid >> 5, lane = tid & 31;
    const int g = lane >> 2, ig2 = (lane & 3) * 2;
    const int warp_m = wid >> 1, warp_n = wid & 1;
    const int mbase = blockIdx.y * 128 + warp_m * 32;
    const int nbase = blockIdx.x * 128 + warp_n * 64;
    const __half* A = (const __half*)g_feats16;

    float d[2][8][4] = {};
    for (int k0 = 0; k0 < NC; k0 += 16) {
        unsigned a[2][4], b[8][2];
#pragma unroll
        for (int mi = 0; mi < 2; mi++) {
            const __half* ap = A + (size_t)(mbase + mi * 16 + g) * NC + k0 + ig2;
            a[mi][0] = *(const unsigned*)ap;
            a[mi][1] = *(const unsigned*)(ap + 8 * NC);
            a[mi][2] = *(const unsigned*)(ap + 8);
            a[mi][3] = *(const unsigned*)(ap + 8 * NC + 8);
        }
#pragma unroll
        for (int nj = 0; nj < 8; nj++) {
            const __half* bp = g_i2h16 + (size_t)(nbase + nj * 8 + g) * NC + k0 + ig2;
            b[nj][0] = *(const unsigned*)bp;
            b[nj][1] = *(const unsigned*)(bp + 8);
        }
#pragma unroll
        for (int mi = 0; mi < 2; mi++)
#pragma unroll
            for (int nj = 0; nj < 8; nj++)
                asm volatile(
                    "mma.sync.aligned.m16n8k16.row.col.f32.f16.f16.f32 "
                    "{%0,%1,%2,%3},{%4,%5,%6,%7},{%8,%9},{%0,%1,%2,%3};"
                    : "+f"(d[mi][nj][0]), "+f"(d[mi][nj][1]),
                      "+f"(d[mi][nj][2]), "+f"(d[mi][nj][3])
                    : "r"(a[mi][0]), "r"(a[mi][1]), "r"(a[mi][2]), "r"(a[mi][3]),
                      "r"(b[nj][0]), "r"(b[nj][1]));
    }
#pragma unroll
    for (int mi = 0; mi < 2; mi++) {
        int r = mbase + mi * 16 + g;
#pragma unroll
        for (int nj = 0; nj < 8; nj++) {
            int c = nbase + nj * 8 + ig2;
            *(__half2*)(g_fp16 + (size_t)r * HID + c) =
                __floats2half2_rn(d[mi][nj][0], d[mi][nj][1]);
            *(__half2*)(g_fp16 + (size_t)(r + 8) * HID + c) =
                __floats2half2_rn(d[mi][nj][2], d[mi][nj][3]);
        }
    }
}

// ---------------- GRU update (hold from smem) ----------------
__device__ __forceinline__ float gru_one(int b, int h, float hold,
                                         const float* __restrict__ gru_b_ih,
                                         const float* __restrict__ gru_b_hh)
{
    size_t base = (size_t)b * GRU3;
    float ir = __ldg(gru_b_ih + h);
    float iz = __ldg(gru_b_ih + HID + h);
    float in = __ldg(gru_b_ih + 2 * HID + h);
#pragma unroll
    for (int p = 0; p < 10; p++) {
        ir += __ldcg(&g_gip[p][base + h]);
        iz += __ldcg(&g_gip[p][base + HID + h]);
        in += __ldcg(&g_gip[p][base + 2 * HID + h]);
    }
    float hr = __ldg(gru_b_hh + h)           + __ldcg(&g_gh[0][base + h])           + __ldcg(&g_gh[1][base + h]);
    float hz = __ldg(gru_b_hh + HID + h)     + __ldcg(&g_gh[0][base + HID + h])     + __ldcg(&g_gh[1][base + HID + h]);
    float hn = __ldg(gru_b_hh + 2 * HID + h) + __ldcg(&g_gh[0][base + 2 * HID + h]) + __ldcg(&g_gh[1][base + 2 * HID + h]);
    float rr = fsig(ir + hr);
    float zz = fsig(iz + hz);
    float nn = ftanh(in + rr * hn);
    return (1.f - zz) * nn + zz * hold;
}

// ---------------- B-CTA GEMM job ----------------
__device__ __forceinline__ void run_job(int j, int step, int tid)
{
    if (j < 480) {
        // splits: 0-3 feats(K 0..512, ki 8) -> rdy_xf ; 4-5 pose+emb(512..896, ki 12) -> rdy_x ;
        //         6-9 crops(896..1472, ki 9) -> rdy_xr
        const int kb[10] = {0, 128, 256, 384, 512, 704, 896, 1040, 1184, 1328};
        const int ki[10] = {8, 8, 8, 8, 12, 12, 9, 9, 9, 9};
        int ks = j / 48, r = j % 48, mt = r / 12, nt = r % 12;
        const unsigned* ctr = (ks < 4) ? &g_rdy_xf[mt * 32]
                            : (ks < 6) ? &g_rdy_x[mt * 32]
                                       : &g_rdy_xr[mt * 32];
        if (tid == 0) spin_ge(ctr, 64u * (step + 1));
        __syncthreads();
        gemm64h(g_x16, RNN_IN, g_wih16, RNN_IN, g_gip[ks], GRU3,
                mt * 64, nt * 64, kb[ks], ki[ks], tid);
        __syncthreads();
        if (tid == 0) atom_inc_rel(&g_rdy_gi[mt * 32]);
    } else {
        int jj = j - 480;
        int ks = jj / 48, r = jj % 48, mt = r / 12, nt = r % 12;
        if (tid == 0) spin_ge(&g_rdy_h[mt * 32], 64u * (step + 1));
        __syncthreads();
        gemm64h(g_hidden16, HID, g_whh16, HID, g_gh[ks], GRU3,
                mt * 64, nt * 64, ks * 128, 8, tid);
        __syncthreads();
        if (tid == 0) atom_inc_rel(&g_rdy_gi[mt * 32]);
    }
}

// ---------------- persistent decode kernel ----------------
__global__ __launch_bounds__(256, 4) void decode_kernel(
    const float* __restrict__ pose,
    const float* __restrict__ pyr0,
    const float* __restrict__ pyr1,
    const float* __restrict__ pyr2,
    const int*   __restrict__ text,
    const float* __restrict__ h2h_b,
    const float* __restrict__ score_w,
    const float* __restrict__ pose_w,   const float* __restrict__ pose_b,
    const float* __restrict__ gru_b_ih, const float* __restrict__ gru_b_hh,
    const float* __restrict__ char_emb,
    const float* __restrict__ gen_w,    const float* __restrict__ gen_b,
    float* __restrict__ out)
{
    __shared__ __align__(16) float sm[4352];
    __shared__ float s_coord[4];
    __shared__ float s_ly[3][2], s_lx[3][2];
    __shared__ int   s_y0[3][2], s_y1[3][2], s_x0[3][2], s_x1[3][2];
    __shared__ int   s_vy[3][2], s_vx[3][2];

    const int tid = threadIdx.x;
    const int bid = blockIdx.x;
    const int lane = tid & 31;
    const int wid = tid >> 5;

    float* h_s   = sm;          // persistent hidden (per A-CTA)
    float* hp_s  = sm + 256;
    float* al    = sm + 512;
    float* ctx_s = sm + 640;
    float* red   = sm + 1408;

    // ---- prologue: counters, hidden16, pose transpose ----
    if (bid == 0) {
        for (int i = tid; i < 4 * 32; i += 256) {
            g_rdy_h[i] = 0u; g_rdy_xf[i] = 0u; g_rdy_x[i] = 0u;
            g_rdy_xr[i] = 0u; g_rdy_gi[i] = 0u;
        }
    }
    if (bid < 256) g_hidden16[bid * 256 + tid] = __float2half(0.f);
    for (int job = bid; job < NB * 32; job += NCTA) {
        int b = job >> 5;
        int r = job & 31;
        int t0 = (r & 3) * 32;
        int p0 = (r >> 2) * 32;
        int y = tid >> 5, x = tid & 31;
#pragma unroll
        for (int q = 0; q < 4; q++) {
            int yy = y + q * 8;
            red[yy * 33 + x] = __ldg(pose + ((size_t)b * POSE + (p0 + yy)) * NT + (t0 + x));
        }
        __syncthreads();
#pragma unroll
        for (int q = 0; q < 4; q++) {
            int yy = y + q * 8;
            g_pose16T[((size_t)(t0 + yy) * NB + b) * POSE + (p0 + x)] =
                __float2half(red[x * 33 + yy]);
        }
        __syncthreads();
    }
    h_s[tid] = 0.f;     // persistent smem hidden init
    gbar();

    if (bid < NB) {
        // ================= A-CTA: full recurrence for b = bid =================
        const int b = bid;
        const int mt = b >> 6;
        for (int step = 0; step < NSTEPS; step++) {
            if (step > 0) {
                if (tid == 0) spin_ge(&g_rdy_gi[mt * 32], 144u * (unsigned)step);
                __syncthreads();
                float hnew = gru_one(b, tid, h_s[tid], gru_b_ih, gru_b_hh);
                g_hidden16[(size_t)b * HID + tid] = __float2half(hnew);
                h_s[tid] = hnew;
                __syncthreads();
                if (tid == 0) atom_inc_rel(&g_rdy_h[mt * 32]);
                g_hs[((size_t)b * NSTEPS + step - 1) * HID + tid] = hnew;
                const uint4* w4 = (const uint4*)(g_h2h16 + (size_t)tid * HID);
                float acc = 0.f;
#pragma unroll 8
                for (int q = 0; q < 32; q++) {
                    uint4 u = __ldg(w4 + q);
                    const __half2* hh = (const __half2*)&u;
                    int bb = q * 8;
                    float2 f0 = __half22float2(hh[0]);
                    float2 f1 = __half22float2(hh[1]);
                    float2 f2 = __half22float2(hh[2]);
                    float2 f3 = __half22float2(hh[3]);
                    acc += f0.x * h_s[bb]     + f0.y * h_s[bb + 1]
                         + f1.x * h_s[bb + 2] + f1.y * h_s[bb + 3]
                         + f2.x * h_s[bb + 4] + f2.y * h_s[bb + 5]
                         + f3.x * h_s[bb + 6] + f3.y * h_s[bb + 7];
                }
                hp_s[tid] = acc + __ldg(h2h_b + tid);
            } else {
                if (tid == 0) atom_inc_rel(&g_rdy_h[mt * 32]);
                hp_s[tid] = __ldg(h2h_b + tid);
            }
            __syncthreads();

            // emb (safe: previous-step consumers finished per gi-counter spin)
            int tgt = (step == 0) ? 0 : (__ldg(text + b * NSTEPS + step - 1) + 1);
            if (tid < EMB)
                g_x16[(size_t)b * RNN_IN + 768 + tid] =
                    __float2half(__ldg(char_emb + (size_t)tgt * EMB + tid));

            // energy
            {
                float4 hpa = *(const float4*)&hp_s[lane * 8];
                float4 hpb = *(const float4*)&hp_s[lane * 8 + 4];
                __half2 hph[4] = {
                    __floats2half2_rn(hpa.x, hpa.y), __floats2half2_rn(hpa.z, hpa.w),
                    __floats2half2_rn(hpb.x, hpb.y), __floats2half2_rn(hpb.z, hpb.w)};
                float4 swa = __ldg((const float4*)(score_w + lane * 8));
                float4 swb = __ldg((const float4*)(score_w + lane * 8 + 4));
                float swf[8] = {swa.x, swa.y, swa.z, swa.w, swb.x, swb.y, swb.z, swb.w};
#pragma unroll
                for (int i = 0; i < 16; i++) {
                    int t = wid * 16 + i;
                    uint4 fv = __ldg((const uint4*)(g_fp16 + ((size_t)t * NB + b) * HID + lane * 8));
                    __half2 v0 = *(__half2*)&fv.x, v1 = *(__half2*)&fv.y;
                    __half2 v2 = *(__half2*)&fv.z, v3 = *(__half2*)&fv.w;
                    float2 t0 = __half22float2(htanh2(__hadd2(v0, hph[0])));
                    float2 t1 = __half22float2(htanh2(__hadd2(v1, hph[1])));
                    float2 t2 = __half22float2(htanh2(__hadd2(v2, hph[2])));
                    float2 t3 = __half22float2(htanh2(__hadd2(v3, hph[3])));
                    float s = t0.x * swf[0] + t0.y * swf[1] + t1.x * swf[2] + t1.y * swf[3]
                            + t2.x * swf[4] + t2.y * swf[5] + t3.x * swf[6] + t3.y * swf[7];
#pragma unroll
                    for (int o = 16; o; o >>= 1) s += __shfl_xor_sync(~0u, s, o);
                    if (!lane) al[t] = s;
                }
            }
            __syncthreads();
            if (wid == 0) {
                float ev[4];
#pragma unroll
                for (int q = 0; q < 4; q++) ev[q] = al[lane + 32 * q];
                float mx = fmaxf(fmaxf(ev[0], ev[1]), fmaxf(ev[2], ev[3]));
#pragma unroll
                for (int o = 16; o; o >>= 1) mx = fmaxf(mx, __shfl_xor_sync(~0u, mx, o));
                float ex[4], ssum = 0.f;
#pragma unroll
                for (int q = 0; q < 4; q++) { ex[q] = __expf(ev[q] - mx); ssum += ex[q]; }
#pragma unroll
                for (int o = 16; o; o >>= 1) ssum += __shfl_xor_sync(~0u, ssum, o);
                float inv = __fdividef(1.f, ssum);
#pragma unroll
                for (int q = 0; q < 4; q++) al[lane + 32 * q] = ex[q] * inv;
            }
            __syncthreads();
            // ctx feats
            {
                int tq = tid >> 6, cg = tid & 63;
                float acc[8] = {};
                int t0 = tq * 32;
#pragma unroll 8
                for (int i = 0; i < 32; i++) {
                    int t = t0 + i;
                    uint4 u = __ldg((const uint4*)(g_feats16 + ((size_t)t * NB + b) * (NC / 2)) + cg);
                    float a = al[t];
                    const __half2* h2 = (const __half2*)&u;
#pragma unroll
                    for (int q = 0; q < 4; q++) {
                        float2 f = __half22float2(h2[q]);
                        acc[2 * q]     = fmaf(a, f.x, acc[2 * q]);
                        acc[2 * q + 1] = fmaf(a, f.y, acc[2 * q + 1]);
                    }
                }
#pragma unroll
                for (int q = 0; q < 8; q++) red[tq * 512 + cg * 8 + q] = acc[q];
            }
            __syncthreads();
            {
                int c = tid * 2;
                float s0 = red[c] + red[512 + c] + red[1024 + c] + red[1536 + c];
                float s1 = red[c + 1] + red[512 + c + 1] + red[1024 + c + 1] + red[1536 + c + 1];
                ctx_s[c] = s0; ctx_s[c + 1] = s1;
                *(__half2*)(g_x16 + (size_t)b * RNN_IN + c) = __floats2half2_rn(s0, s1);
            }
            __syncthreads();
            // ---- publish ctx-feats: splits 0-3 can start ----
            if (tid == 0) atom_inc_rel(&g_rdy_xf[mt * 32]);
            // ctx pose
            {
                int tq2 = tid >> 5, cg2 = tid & 31;
                float acc[8] = {};
                int t0 = tq2 * 16;
#pragma unroll 8
                for (int i = 0; i < 16; i++) {
                    int t = t0 + i;
                    uint4 u = __ldg((const uint4*)(g_pose16T + ((size_t)t * NB + b) * POSE) + cg2);
                    float a = al[t];
                    const __half2* h2 = (const __half2*)&u;
#pragma unroll
                    for (int q = 0; q < 4; q++) {
                        float2 f = __half22float2(h2[q]);
                        acc[2 * q]     = fmaf(a, f.x, acc[2 * q]);
                        acc[2 * q + 1] = fmaf(a, f.y, acc[2 * q + 1]);
                    }
                }
#pragma unroll
                for (int q = 0; q < 8; q++) red[tq2 * 256 + cg2 * 8 + q] = acc[q];
            }
            __syncthreads();
            {
                int c = tid;
                float s = 0.f;
#pragma unroll
                for (int q = 0; q < 8; q++) s += red[q * 256 + c];
                ctx_s[NC + c] = s;
                g_x16[(size_t)b * RNN_IN + NC + c] = __float2half(s);
            }
            __syncthreads();
            // ---- publish ctx-pose + emb: splits 4-5 can start ----
            if (tid == 0) atom_inc_rel(&g_rdy_x[mt * 32]);
            // coord
            if (wid < 4) {
                const float* pw = pose_w + wid * 768;
                float s = 0.f;
#pragma unroll
                for (int q = 0; q < 24; q++) { int c = lane + q * 32; s += ctx_s[c] * __ldg(pw + c); }
#pragma unroll
                for (int o = 16; o; o >>= 1) s += __shfl_xor_sync(~0u, s, o);
                if (!lane) s_coord[wid] = fsig(s + __ldg(pose_b + wid));
            }
            __syncthreads();
            if (tid == 0) {
                const int Hs[3] = {16, 8, 4};
                const int Ws[3] = {128, 64, 65};
                float c0 = s_coord[0], c1 = s_coord[1], c2 = s_coord[2], c3 = s_coord[3];
                for (int p = 0; p < 3; p++) {
                    float Hf = (float)Hs[p], Wf = (float)Ws[p];
                    c0 *= Hf; c1 *= Wf; c2 *= Hf; c3 *= Wf;
                    float x1 = c0, y1 = c1, x2 = c2, y2 = c3;
                    float bw = fmaxf(x2 - x1, 1.f) * 0.5f;
                    float bh = fmaxf(y2 - y1, 1.f) * 0.5f;
#pragma unroll
                    for (int i = 0; i < 2; i++) {
                        float ys = y1 + (0.5f + (float)i) * bh;
                        s_vy[p][i] = (ys >= -1.f && ys <= Hf) ? 1 : 0;
                        float y = fminf(fmaxf(ys, 0.f), Hf - 1.f);
                        float y0f = floorf(y);
                        int y0i = (int)y0f;
                        s_y0[p][i] = y0i;
                        s_y1[p][i] = min(y0i + 1, Hs[p] - 1);
                        s_ly[p][i] = y - y0f;
                        float xs = x1 + (0.5f + (float)i) * bw;
                        s_vx[p][i] = (xs >= -1.f && xs <= Wf) ? 1 : 0;
                        float x = fminf(fmaxf(xs, 0.f), Wf - 1.f);
                        float x0f = floorf(x);
                        int x0i = (int)x0f;
                        s_x0[p][i] = x0i;
                        s_x1[p][i] = min(x0i + 1, Ws[p] - 1);
                        s_lx[p][i] = x - x0f;
                    }
                }
            }
            __syncthreads();
            for (int o = tid; o < 576; o += 256) {
                int p, local;
                if (o < 64)       { p = 0; local = o; }
                else if (o < 320) { p = 1; local = o - 64; }
                else              { p = 2; local = o - 320; }
                int c = local >> 2;
                int ij = local & 3;
                int i = ij >> 1, j = ij & 1;
                float val = 0.f;
                if (s_vy[p][i] && s_vx[p][j]) {
                    float ly = s_ly[p][i], lx = s_lx[p][j];
                    float hy = 1.f - ly, hx = 1.f - lx;
                    int y0 = s_y0[p][i], y1 = s_y1[p][i];
                    int x0 = s_x0[p][j], x1 = s_x1[p][j];
                    const float* f; int W, HW;
                    if (p == 0)      { f = pyr0; W = 128; HW = 16 * 128; }
                    else if (p == 1) { f = pyr1; W = 64;  HW = 8 * 64;  }
                    else             { f = pyr2; W = 65;  HW = 4 * 65;  }
                    const float* fc = f + (size_t)c * HW;
                    val = fc[y0 * W + x0] * (hy * hx)
                        + fc[y0 * W + x1] * (hy * lx)
                        + fc[y1 * W + x0] * (ly * hx)
                        + fc[y1 * W + x1] * (ly * lx);
                }
                g_x16[(size_t)b * RNN_IN + 896 + o] = __float2half(val);
            }
            __syncthreads();
            if (tid == 0) atom_inc_rel(&g_rdy_xr[mt * 32]);
        }
        // final GRU
        if (tid == 0) spin_ge(&g_rdy_gi[mt * 32], 144u * NSTEPS);
        __syncthreads();
        float hnew = gru_one(b, tid, h_s[tid], gru_b_ih, gru_b_hh);
        g_hs[((size_t)b * NSTEPS + NSTEPS - 1) * HID + tid] = hnew;
    } else {
        // ================= B-CTA: 1-2 GEMM tiles per step =================
        int j1 = bid - 256;
        int j2 = j1 + 336;
        bool has2 = (j2 < 576);
        int ja = j1, jb = has2 ? j2 : -1;
        if (has2 && j2 >= 480) { ja = j2; jb = j1; }  // gh first (ready earlier)
        for (int step = 0; step < NSTEPS; step++) {
            run_job(ja, step, tid);
            if (jb >= 0) run_job(jb, step, tid);
        }
    }
    gbar();

    // ===== final classifier =====
    {
        int gw = bid * 8 + wid;
        for (int m = gw; m < NB * NSTEPS; m += NWARP) {
            const float* hrow = g_hs + (size_t)m * HID;
            float a[8];
#pragma unroll
            for (int q = 0; q < 8; q++) a[q] = __ldcg(hrow + lane + q * 32);
            for (int n = 0; n < NCLS; n++) {
                const float* w = gen_w + (size_t)n * HID;
                float s = 0.f;
#pragma unroll
                for (int q = 0; q < 8; q++) s += a[q] * __ldg(w + lane + q * 32);
#pragma unroll
                for (int o = 16; o; o >>= 1) s += __shfl_xor_sync(~0u, s, o);
                if (!lane) out[(size_t)m * NCLS + n] = s + gen_b[n];
            }
        }
    }
}

// ---------------- driver ----------------
extern "C" void kernel_launch(void* const* d_in, const int* in_sizes, int n_in,
                              void* d_out, int out_size)
{
    const float* feats    = (const float*)d_in[0];
    const float* pose     = (const float*)d_in[1];
    const float* pyr0     = (const float*)d_in[2];
    const float* pyr1     = (const float*)d_in[3];
    const float* pyr2     = (const float*)d_in[4];
    const int*   text     = (const int*)  d_in[6];
    const float* i2h_w    = (const float*)d_in[7];
    const float* h2h_w    = (const float*)d_in[8];
    const float* h2h_b    = (const float*)d_in[9];
    const float* score_w  = (const float*)d_in[10];
    const float* pose_w   = (const float*)d_in[11];
    const float* pose_b   = (const float*)d_in[12];
    const float* gru_w_ih = (const float*)d_in[13];
    const float* gru_w_hh = (const float*)d_in[14];
    const float* gru_b_ih = (const float*)d_in[15];
    const float* gru_b_hh = (const float*)d_in[16];
    const float* char_emb = (const float*)d_in[17];
    const float* gen_w    = (const float*)d_in[18];
    const float* gen_b    = (const float*)d_in[19];
    float* out = (float*)d_out;

    convert_kernel<<<1184, 256>>>(feats, i2h_w, h2h_w, gru_w_ih, gru_w_hh);

    dim3 g1(2, 256);
    fp_gemm_hmma<<<g1, 256>>>();

    decode_kernel<<<NCTA, 256>>>(pose, pyr0, pyr1, pyr2, text,
                                 h2h_b, score_w, pose_w, pose_b,
                                 gru_b_ih, gru_b_hh,
                                 char_emb, gen_w, gen_b, out);
}